// round 14
// baseline (speedup 1.0000x reference)
#include <cuda_runtime.h>
#include <cstdint>

#define F_DIM 513
#define T_DIM 256
#define C_DIM 8
#define N_DIM 4
#define TF (T_DIM * F_DIM)        // 131328
#define NF (N_DIM * F_DIM)        // 2052
#define DIAG_LOAD 7.0710678118654755e-4f  // 0.001/sqrt(2)

#define STEP_FLOATS (16 * 16 * 32)   // 8192 floats = 32 KB per pipeline step
#define NBUF 3
#define COV_SMEM (NBUF * STEP_FLOATS * 4)   // 96 KB

// FINAL covariances (already /T): [input(2)][n(4)][entry(64)][f(513)]
__device__ float g_cov[2 * N_DIM * 64 * F_DIM];
// conj(W): [n][c][{re,im}][f]
__device__ float g_wc[N_DIM * C_DIM * 2 * F_DIM];

// ---- packed fp32x2 helpers (FFMA2 is PTX-only) ----
__device__ __forceinline__ unsigned long long pack2(float lo, float hi) {
    unsigned long long r;
    asm("mov.b64 %0, {%1, %2};" : "=l"(r) : "f"(lo), "f"(hi));
    return r;
}
__device__ __forceinline__ void fma2(unsigned long long& acc,
                                     unsigned long long a, unsigned long long b) {
    asm("fma.rn.f32x2 %0, %1, %2, %0;" : "+l"(acc) : "l"(a), "l"(b));
}
__device__ __forceinline__ void unpack2(unsigned long long v, float& lo, float& hi) {
    asm("mov.b64 {%0, %1}, %2;" : "=f"(lo), "=f"(hi) : "l"(v));
}

// ---- cp.async helpers ----
__device__ __forceinline__ void cp_async4(uint32_t smem_addr, const float* gptr) {
    asm volatile("cp.async.ca.shared.global [%0], [%1], 4;"
                 :: "r"(smem_addr), "l"(gptr));
}
__device__ __forceinline__ void cp_commit() {
    asm volatile("cp.async.commit_group;");
}
template <int N>
__device__ __forceinline__ void cp_wait() {
    asm volatile("cp.async.wait_group %0;" :: "n"(N));
}

// -------------------------------------------------------------------------
// Pass 1: fused covariance with a cp.async 3-deep pipeline.
// Block 512 = 32 f (fx) x 16 t-slices (sl). Per step s, each thread stages
// ITS OWN 16 plane values for t = sl*16+s into smem (no cross-thread data
// -> no per-step __syncthreads), then computes the previous step's t with
// the f32x2 Hermitian update. 16 steps. Then cross-slice smem reduction.
// grid (17, 8) = 136 blocks, 1 block/SM, 96 KB dynamic smem.
// -------------------------------------------------------------------------
__global__ __launch_bounds__(512, 1) void cov_fused_kernel(
    const float* __restrict__ target, const float* __restrict__ noise)
{
    extern __shared__ float sb[];        // [NBUF][16 planes][16 sl][32 fx]
    int tid = threadIdx.x;
    int fx  = tid & 31;
    int sl  = tid >> 5;
    int gf  = blockIdx.x * 32 + fx;
    int fc  = min(gf, F_DIM - 1);
    int inp = blockIdx.y & 1;
    int n   = blockIdx.y >> 1;
    const float* src = inp ? noise : target;

    uint32_t sbase;
    asm("{ .reg .u64 t0; cvta.to.shared.u64 t0, %1; cvt.u32.u64 %0, t0; }"
        : "=r"(sbase) : "l"(sb));

    const float* basep = src + (size_t)(16 * n) * TF + fc;

    unsigned long long acc[28], dd[8];
#pragma unroll
    for (int k = 0; k < 28; k++) acc[k] = 0ull;
#pragma unroll
    for (int c = 0; c < 8; c++) dd[c] = 0ull;

    // stage step s into buffer b: 16 planes of own (sl, fx)
    auto stage = [&](int s, int b) {
        const float* g0 = basep + (size_t)(sl * 16 + s) * F_DIM;
        uint32_t d0 = sbase + (uint32_t)(b * STEP_FLOATS + sl * 32 + fx) * 4u;
#pragma unroll
        for (int r = 0; r < 16; r++)
            cp_async4(d0 + (uint32_t)(r * 512) * 4u, g0 + (size_t)r * TF);
        cp_commit();
    };

    stage(0, 0);
    stage(1, 1);

#pragma unroll
    for (int s = 0; s < 16; s++) {
        if (s + 2 < 16) stage(s + 2, (s + 2) % NBUF);
        if (s < 14)      cp_wait<2>();
        else if (s == 14) cp_wait<1>();
        else              cp_wait<0>();

        const float* buf = sb + (s % NBUF) * STEP_FLOATS + sl * 32 + fx;
        float x[16];
#pragma unroll
        for (int v = 0; v < 16; v++)
            x[v] = buf[v * 512];

        unsigned long long P[8], Q[8];
#pragma unroll
        for (int c = 0; c < 8; c++) {
            P[c] = pack2(x[c], x[8 + c]);
            Q[c] = pack2(x[8 + c], -x[c]);
            fma2(dd[c], P[c], P[c]);
        }
#pragma unroll
        for (int j = 1; j < 8; j++) {
            unsigned long long BR = pack2(x[j], x[j]);
            unsigned long long BI = pack2(x[8 + j], x[8 + j]);
#pragma unroll
            for (int i = 0; i < j; i++) {
                int kk = 7 * i - (i * (i - 1)) / 2 + (j - i - 1);
                fma2(acc[kk], P[i], BR);
                fma2(acc[kk], Q[i], BI);
            }
        }
    }

    float d[8], orr[28], oii[28];
#pragma unroll
    for (int c = 0; c < 8; c++) {
        float a, b; unpack2(dd[c], a, b); d[c] = a + b;
    }
#pragma unroll
    for (int k = 0; k < 28; k++) unpack2(acc[k], orr[k], oii[k]);

    __syncthreads();                     // all compute done before smem reuse

    // Cross-slice reduction, 4 batches of 16 entries (reuses sb, 32 KB).
    float (*sred)[16][32] = (float(*)[16][32])sb;
    float* gout = g_cov + (size_t)(inp * N_DIM + n) * 64 * F_DIM;
    const float invT = 1.0f / (float)T_DIM;

#pragma unroll
    for (int b = 0; b < 4; b++) {
#pragma unroll
        for (int q = 0; q < 16; q++) {
            int e = b * 16 + q;
            float v = (e < 8) ? d[e] : (e < 36 ? orr[e - 8] : oii[e - 36]);
            sred[q][sl][fx] = v;
        }
        __syncthreads();
        {
            float sv = 0.f;
#pragma unroll
            for (int s = 0; s < 16; s++) sv += sred[sl][s][fx];
            if (gf < F_DIM)
                gout[(size_t)(b * 16 + sl) * F_DIM + gf] = sv * invT;
        }
        __syncthreads();
    }
}

// -------------------------------------------------------------------------
// Pass 2: per-(n,f) solve. Block = 256 thr = 8 matrices -> 257 blocks.
// -------------------------------------------------------------------------
__global__ __launch_bounds__(256) void solve_kernel(const int* __restrict__ ref_idx)
{
    __shared__ float s_cov[2][64][9];    // [input][entry][matrix + pad]
    int tid = threadIdx.x;
    int m0  = blockIdx.x * 8;

#pragma unroll
    for (int r = 0; r < 4; r++) {
        int o  = r * 256 + tid;
        int mi = o & 7;
        int e  = (o >> 3) & 63;
        int ip = o >> 9;
        int m  = min(m0 + mi, NF - 1);
        int n  = m / F_DIM, f = m % F_DIM;
        s_cov[ip][e][mi] =
            g_cov[((size_t)(ip * N_DIM + n) * 64 + e) * F_DIM + f];
    }
    __syncthreads();

    if (tid >= 64) return;
    int mi = tid >> 3;
    int i  = tid & 7;
    int m  = min(m0 + mi, NF - 1);
    int n  = m / F_DIM, f = m % F_DIM;
    const unsigned FULL = 0xffffffffu;

    float nr[8], ni[8];
#pragma unroll
    for (int j = 0; j < 8; j++) {
        if (j == i) { nr[j] = s_cov[1][i][mi] + DIAG_LOAD; ni[j] = DIAG_LOAD; }
        else {
            int a = min(i, j), b = max(i, j);
            int kk = 7 * a - (a * (a - 1)) / 2 + (b - a - 1);
            float sign = (i < j) ? 1.f : -1.f;
            nr[j] = s_cov[1][8 + kk][mi];
            ni[j] = sign * s_cov[1][36 + kk][mi];
        }
    }

#pragma unroll
    for (int kp = 0; kp < 8; kp++) {
        float akk_r = __shfl_sync(FULL, nr[kp], kp, 8);
        float akk_i = __shfl_sync(FULL, ni[kp], kp, 8);
        float idn = 1.0f / fmaf(akk_r, akk_r, akk_i * akk_i);
        float p_r = akk_r * idn, p_i = -akk_i * idn;
        float s_r[8], s_i[8];
#pragma unroll
        for (int j = 0; j < 8; j++) {
            float ar = __shfl_sync(FULL, nr[j], kp, 8);
            float ai = __shfl_sync(FULL, ni[j], kp, 8);
            s_r[j] = ar * p_r - ai * p_i;
            s_i[j] = ar * p_i + ai * p_r;
        }
        if (i == kp) {
#pragma unroll
            for (int j = 0; j < 8; j++) { nr[j] = s_r[j]; ni[j] = s_i[j]; }
            nr[kp] = p_r; ni[kp] = p_i;
        } else {
            float f_r = nr[kp], f_i = ni[kp];
#pragma unroll
            for (int j = 0; j < 8; j++) {
                if (j == kp) continue;
                nr[j] -= f_r * s_r[j] - f_i * s_i[j];
                ni[j] -= f_r * s_i[j] + f_i * s_r[j];
            }
            nr[kp] = -(f_r * p_r - f_i * p_i);
            ni[kp] = -(f_r * p_i + f_i * p_r);
        }
    }

    float tr_[8], ti[8];
#pragma unroll
    for (int j = 0; j < 8; j++) {
        if (j == i) { tr_[j] = s_cov[0][i][mi]; ti[j] = 0.f; }
        else {
            int a = min(i, j), b = max(i, j);
            int kk = 7 * a - (a * (a - 1)) / 2 + (b - a - 1);
            float sign = (i < j) ? 1.f : -1.f;
            tr_[j] = s_cov[0][8 + kk][mi];
            ti[j]  = sign * s_cov[0][36 + kk][mi];
        }
    }

    float trc_r = 0.f, trc_i = 0.f;
#pragma unroll
    for (int j = 0; j < 8; j++) {
        trc_r += nr[j] * tr_[j] + ni[j] * ti[j];
        trc_i += ni[j] * tr_[j] - nr[j] * ti[j];
    }
#pragma unroll
    for (int off = 4; off > 0; off >>= 1) {
        trc_r += __shfl_xor_sync(FULL, trc_r, off, 8);
        trc_i += __shfl_xor_sync(FULL, trc_i, off, 8);
    }

    int ref = *ref_idx;
    float pr = 0.f, pi = 0.f;
#pragma unroll
    for (int jj = 0; jj < 8; jj++)
        if (jj == ref) { pr = tr_[jj]; pi = ti[jj]; }

    float w_r = 0.f, w_i = 0.f;
#pragma unroll
    for (int j = 0; j < 8; j++) {
        float br = __shfl_sync(FULL, pr, j, 8);
        float bi = __shfl_sync(FULL, pi, j, 8);
        w_r += nr[j] * br - ni[j] * bi;
        w_i += nr[j] * bi + ni[j] * br;
    }

    float ldn = 1.0f / fmaf(trc_r, trc_r, trc_i * trc_i);
    float lr = trc_r * ldn, li = -trc_i * ldn;
    float Wr = w_r * lr - w_i * li;
    float Wi = w_r * li + w_i * lr;

    g_wc[((n * 8 + i) * 2 + 0) * F_DIM + f] = Wr;
    g_wc[((n * 8 + i) * 2 + 1) * F_DIM + f] = -Wi;
}

// -------------------------------------------------------------------------
// Pass 3: beamform, TPER=2 (best measured), loads hoisted.
// grid (5, 128, 4) = 2560 blocks of 128.
// -------------------------------------------------------------------------
#define TPER 2
__global__ __launch_bounds__(128) void beamform_kernel(
    const float* __restrict__ mix, float* __restrict__ out)
{
    int f = blockIdx.x * blockDim.x + threadIdx.x;
    if (f >= F_DIM) return;
    int n  = blockIdx.z;
    int t0 = blockIdx.y * TPER;

    float wr[8], wi[8];
#pragma unroll
    for (int c = 0; c < 8; c++) {
        wr[c] = g_wc[((n * 8 + c) * 2 + 0) * F_DIM + f];
        wi[c] = g_wc[((n * 8 + c) * 2 + 1) * F_DIM + f];
    }

    const float* baseR = mix + (size_t)(16 * n) * TF + f;
    const float* baseI = mix + (size_t)(16 * n + 8) * TF + f;
    float* outR = out + (size_t)(2 * n) * TF + f;      // (N,2,1,T,F)
    float* outI = out + (size_t)(2 * n + 1) * TF + f;

    float yr[TPER][8], yi[TPER][8];
#pragma unroll
    for (int dt = 0; dt < TPER; dt++) {
        int off = (t0 + dt) * F_DIM;
#pragma unroll
        for (int c = 0; c < 8; c++) {
            yr[dt][c] = __ldg(baseR + (size_t)c * TF + off);
            yi[dt][c] = __ldg(baseI + (size_t)c * TF + off);
        }
    }
#pragma unroll
    for (int dt = 0; dt < TPER; dt++) {
        float Xr = 0.f, Xi = 0.f;
#pragma unroll
        for (int c = 0; c < 8; c++) {
            Xr += wr[c] * yr[dt][c] - wi[c] * yi[dt][c];
            Xi += wr[c] * yi[dt][c] + wi[c] * yr[dt][c];
        }
        int off = (t0 + dt) * F_DIM;
        outR[off] = Xr;
        outI[off] = Xi;
    }
}

// -------------------------------------------------------------------------
extern "C" void kernel_launch(void* const* d_in, const int* in_sizes, int n_in,
                              void* d_out, int out_size)
{
    const float* mixture = (const float*)d_in[0];
    const float* target  = (const float*)d_in[1];
    const float* noise   = (const float*)d_in[2];
    const int*   ref     = (const int*)d_in[3];
    float* out = (float*)d_out;

    // idempotent, safe under capture
    cudaFuncSetAttribute(cov_fused_kernel,
                         cudaFuncAttributeMaxDynamicSharedMemorySize, COV_SMEM);

    dim3 g1((F_DIM + 31) / 32, N_DIM * 2);   // 17 x 8 = 136 blocks
    cov_fused_kernel<<<g1, 512, COV_SMEM>>>(target, noise);

    int groups = (NF + 7) / 8;                // 257 blocks
    solve_kernel<<<groups, 256>>>(ref);

    dim3 g3((F_DIM + 127) / 128, T_DIM / TPER, N_DIM);
    beamform_kernel<<<g3, 128>>>(mixture, out);
}

// round 15
// speedup vs baseline: 2.9218x; 2.9218x over previous
#include <cuda_runtime.h>

#define F_DIM 513
#define T_DIM 256
#define C_DIM 8
#define N_DIM 4
#define TF (T_DIM * F_DIM)        // 131328
#define NF (N_DIM * F_DIM)        // 2052
#define DIAG_LOAD 7.0710678118654755e-4f  // 0.001/sqrt(2)
#define GRID 136                   // 17 x 8 <= 148 SMs -> co-resident

// FINAL covariances (already /T): [input(2)][n(4)][entry(64)][f(513)]
__device__ float g_cov[2 * N_DIM * 64 * F_DIM];
// conj(W): [n][c][{re,im}][f]
__device__ float g_wc[N_DIM * C_DIM * 2 * F_DIM];
// grid barrier counter (monotonic across graph replays)
__device__ unsigned int g_bar;

// ---- packed fp32x2 helpers (FFMA2 is PTX-only) ----
__device__ __forceinline__ unsigned long long pack2(float lo, float hi) {
    unsigned long long r;
    asm("mov.b64 %0, {%1, %2};" : "=l"(r) : "f"(lo), "f"(hi));
    return r;
}
__device__ __forceinline__ void fma2(unsigned long long& acc,
                                     unsigned long long a, unsigned long long b) {
    asm("fma.rn.f32x2 %0, %1, %2, %0;" : "+l"(acc) : "l"(a), "l"(b));
}
__device__ __forceinline__ void unpack2(unsigned long long v, float& lo, float& hi) {
    asm("mov.b64 {%0, %1}, %2;" : "=f"(lo), "=f"(hi) : "l"(v));
}

__device__ __forceinline__ void grid_barrier() {
    __syncthreads();
    if (threadIdx.x == 0) {
        __threadfence();
        unsigned old = atomicAdd(&g_bar, 1u);
        unsigned target = (old / GRID + 1u) * GRID;
        while (*(volatile unsigned int*)&g_bar < target) __nanosleep(64);
        __threadfence();
    }
    __syncthreads();
}

// -------------------------------------------------------------------------
// Kernel 1: cov (R11 body, measured 17.8us) + grid barrier + fused solve.
// 136 blocks x 512 thr, 1 block/SM, co-resident.
// -------------------------------------------------------------------------
__global__ __launch_bounds__(512, 1) void cov_solve_kernel(
    const float* __restrict__ target, const float* __restrict__ noise,
    const int* __restrict__ ref_idx)
{
    __shared__ float s_raw[16 * 16 * 32];   // 32 KB, reused across phases
    int tid = threadIdx.x;
    int bx  = blockIdx.x;

    // ===================== Phase 1: covariance (R11) =====================
    {
        int fb = bx % 17;
        int z  = bx / 17;
        int fx = tid & 31;
        int sl = tid >> 5;
        int gf = fb * 32 + fx;
        int fc = min(gf, F_DIM - 1);
        int inp = z & 1;
        int n   = z >> 1;
        const float* src = inp ? noise : target;
        int t0 = sl * 16;

        unsigned long long acc[28], dd[8];
#pragma unroll
        for (int k = 0; k < 28; k++) acc[k] = 0ull;
#pragma unroll
        for (int c = 0; c < 8; c++) dd[c] = 0ull;

        const float* base = src + (size_t)(16 * n) * TF + fc + (size_t)t0 * F_DIM;

#pragma unroll
        for (int tt = 0; tt < 16; ++tt) {
            const float* p = base + (size_t)tt * F_DIM;
            float x[16];
#pragma unroll
            for (int v = 0; v < 16; v++)
                x[v] = __ldg(p + (size_t)v * TF);

            unsigned long long P[8], Q[8];
#pragma unroll
            for (int c = 0; c < 8; c++) {
                P[c] = pack2(x[c], x[8 + c]);
                Q[c] = pack2(x[8 + c], -x[c]);
                fma2(dd[c], P[c], P[c]);
            }
#pragma unroll
            for (int j = 1; j < 8; j++) {
                unsigned long long BR = pack2(x[j], x[j]);
                unsigned long long BI = pack2(x[8 + j], x[8 + j]);
#pragma unroll
                for (int i = 0; i < j; i++) {
                    int kk = 7 * i - (i * (i - 1)) / 2 + (j - i - 1);
                    fma2(acc[kk], P[i], BR);
                    fma2(acc[kk], Q[i], BI);
                }
            }
        }

        float d[8], orr[28], oii[28];
#pragma unroll
        for (int c = 0; c < 8; c++) {
            float a, b; unpack2(dd[c], a, b); d[c] = a + b;
        }
#pragma unroll
        for (int k = 0; k < 28; k++) unpack2(acc[k], orr[k], oii[k]);

        float (*sred)[16][32] = (float(*)[16][32])s_raw;
        float* gout = g_cov + (size_t)(inp * N_DIM + n) * 64 * F_DIM;
        const float invT = 1.0f / (float)T_DIM;

#pragma unroll
        for (int b = 0; b < 4; b++) {
#pragma unroll
            for (int q = 0; q < 16; q++) {
                int e = b * 16 + q;
                float v = (e < 8) ? d[e] : (e < 36 ? orr[e - 8] : oii[e - 36]);
                sred[q][sl][fx] = v;
            }
            __syncthreads();
            {
                float sv = 0.f;
#pragma unroll
                for (int s = 0; s < 16; s++) sv += sred[sl][s][fx];
                if (gf < F_DIM)
                    gout[(size_t)(b * 16 + sl) * F_DIM + gf] = sv * invT;
            }
            __syncthreads();
        }
    }

    grid_barrier();

    // ===================== Phase 2: solve (16 matrices / block) ==============
    {
        int m0 = bx * 16;
        if (m0 < NF) {
            float (*s_cov)[64][17] = (float(*)[64][17])s_raw;  // [2][64][17]
#pragma unroll
            for (int r = 0; r < 4; r++) {
                int o  = r * 512 + tid;
                int mi = o & 15;
                int e  = (o >> 4) & 63;
                int ip = o >> 10;
                int m  = min(m0 + mi, NF - 1);
                int n  = m / F_DIM, f = m % F_DIM;
                s_cov[ip][e][mi] =
                    g_cov[((size_t)(ip * N_DIM + n) * 64 + e) * F_DIM + f];
            }
            __syncthreads();

            if (tid < 128) {
                int mi = tid >> 3;
                int i  = tid & 7;
                int m  = min(m0 + mi, NF - 1);
                int n  = m / F_DIM, f = m % F_DIM;
                const unsigned FULL = 0xffffffffu;

                float nr[8], ni[8];
#pragma unroll
                for (int j = 0; j < 8; j++) {
                    if (j == i) { nr[j] = s_cov[1][i][mi] + DIAG_LOAD; ni[j] = DIAG_LOAD; }
                    else {
                        int a = min(i, j), b = max(i, j);
                        int kk = 7 * a - (a * (a - 1)) / 2 + (b - a - 1);
                        float sign = (i < j) ? 1.f : -1.f;
                        nr[j] = s_cov[1][8 + kk][mi];
                        ni[j] = sign * s_cov[1][36 + kk][mi];
                    }
                }

#pragma unroll
                for (int kp = 0; kp < 8; kp++) {
                    float akk_r = __shfl_sync(FULL, nr[kp], kp, 8);
                    float akk_i = __shfl_sync(FULL, ni[kp], kp, 8);
                    float idn = 1.0f / fmaf(akk_r, akk_r, akk_i * akk_i);
                    float p_r = akk_r * idn, p_i = -akk_i * idn;
                    float s_r[8], s_i[8];
#pragma unroll
                    for (int j = 0; j < 8; j++) {
                        float ar = __shfl_sync(FULL, nr[j], kp, 8);
                        float ai = __shfl_sync(FULL, ni[j], kp, 8);
                        s_r[j] = ar * p_r - ai * p_i;
                        s_i[j] = ar * p_i + ai * p_r;
                    }
                    if (i == kp) {
#pragma unroll
                        for (int j = 0; j < 8; j++) { nr[j] = s_r[j]; ni[j] = s_i[j]; }
                        nr[kp] = p_r; ni[kp] = p_i;
                    } else {
                        float f_r = nr[kp], f_i = ni[kp];
#pragma unroll
                        for (int j = 0; j < 8; j++) {
                            if (j == kp) continue;
                            nr[j] -= f_r * s_r[j] - f_i * s_i[j];
                            ni[j] -= f_r * s_i[j] + f_i * s_r[j];
                        }
                        nr[kp] = -(f_r * p_r - f_i * p_i);
                        ni[kp] = -(f_r * p_i + f_i * p_r);
                    }
                }

                float tr_[8], ti[8];
#pragma unroll
                for (int j = 0; j < 8; j++) {
                    if (j == i) { tr_[j] = s_cov[0][i][mi]; ti[j] = 0.f; }
                    else {
                        int a = min(i, j), b = max(i, j);
                        int kk = 7 * a - (a * (a - 1)) / 2 + (b - a - 1);
                        float sign = (i < j) ? 1.f : -1.f;
                        tr_[j] = s_cov[0][8 + kk][mi];
                        ti[j]  = sign * s_cov[0][36 + kk][mi];
                    }
                }

                float trc_r = 0.f, trc_i = 0.f;
#pragma unroll
                for (int j = 0; j < 8; j++) {
                    trc_r += nr[j] * tr_[j] + ni[j] * ti[j];
                    trc_i += ni[j] * tr_[j] - nr[j] * ti[j];
                }
#pragma unroll
                for (int off = 4; off > 0; off >>= 1) {
                    trc_r += __shfl_xor_sync(FULL, trc_r, off, 8);
                    trc_i += __shfl_xor_sync(FULL, trc_i, off, 8);
                }

                int ref = *ref_idx;
                float pr = 0.f, pi = 0.f;
#pragma unroll
                for (int jj = 0; jj < 8; jj++)
                    if (jj == ref) { pr = tr_[jj]; pi = ti[jj]; }

                float w_r = 0.f, w_i = 0.f;
#pragma unroll
                for (int j = 0; j < 8; j++) {
                    float br = __shfl_sync(FULL, pr, j, 8);
                    float bi = __shfl_sync(FULL, pi, j, 8);
                    w_r += nr[j] * br - ni[j] * bi;
                    w_i += nr[j] * bi + ni[j] * br;
                }

                float ldn = 1.0f / fmaf(trc_r, trc_r, trc_i * trc_i);
                float lr = trc_r * ldn, li = -trc_i * ldn;
                float Wr = w_r * lr - w_i * li;
                float Wi = w_r * li + w_i * lr;

                g_wc[((n * 8 + i) * 2 + 0) * F_DIM + f] = Wr;
                g_wc[((n * 8 + i) * 2 + 1) * F_DIM + f] = -Wi;
            }
        }
    }
}

// -------------------------------------------------------------------------
// Kernel 2: beamform (R11 body), TPER=2, grid (5, 128, 4) = 2560 blocks.
// -------------------------------------------------------------------------
#define TPER 2
__global__ __launch_bounds__(128) void beamform_kernel(
    const float* __restrict__ mix, float* __restrict__ out)
{
    int f = blockIdx.x * blockDim.x + threadIdx.x;
    if (f >= F_DIM) return;
    int n  = blockIdx.z;
    int t0 = blockIdx.y * TPER;

    float wr[8], wi[8];
#pragma unroll
    for (int c = 0; c < 8; c++) {
        wr[c] = g_wc[((n * 8 + c) * 2 + 0) * F_DIM + f];
        wi[c] = g_wc[((n * 8 + c) * 2 + 1) * F_DIM + f];
    }

    const float* baseR = mix + (size_t)(16 * n) * TF + f;
    const float* baseI = mix + (size_t)(16 * n + 8) * TF + f;
    float* outR = out + (size_t)(2 * n) * TF + f;      // (N,2,1,T,F)
    float* outI = out + (size_t)(2 * n + 1) * TF + f;

    float yr[TPER][8], yi[TPER][8];
#pragma unroll
    for (int dt = 0; dt < TPER; dt++) {
        int off = (t0 + dt) * F_DIM;
#pragma unroll
        for (int c = 0; c < 8; c++) {
            yr[dt][c] = __ldg(baseR + (size_t)c * TF + off);
            yi[dt][c] = __ldg(baseI + (size_t)c * TF + off);
        }
    }
#pragma unroll
    for (int dt = 0; dt < TPER; dt++) {
        float Xr = 0.f, Xi = 0.f;
#pragma unroll
        for (int c = 0; c < 8; c++) {
            Xr += wr[c] * yr[dt][c] - wi[c] * yi[dt][c];
            Xi += wr[c] * yi[dt][c] + wi[c] * yr[dt][c];
        }
        int off = (t0 + dt) * F_DIM;
        outR[off] = Xr;
        outI[off] = Xi;
    }
}

// -------------------------------------------------------------------------
extern "C" void kernel_launch(void* const* d_in, const int* in_sizes, int n_in,
                              void* d_out, int out_size)
{
    const float* mixture = (const float*)d_in[0];
    const float* target  = (const float*)d_in[1];
    const float* noise   = (const float*)d_in[2];
    const int*   ref     = (const int*)d_in[3];
    float* out = (float*)d_out;

    dim3 g1(GRID);                            // 136 blocks, co-resident
    cov_solve_kernel<<<g1, 512>>>(target, noise, ref);

    dim3 g3((F_DIM + 127) / 128, T_DIM / TPER, N_DIM);
    beamform_kernel<<<g3, 128>>>(mixture, out);
}